// round 1
// baseline (speedup 1.0000x reference)
#include <cuda_runtime.h>

#define Hh 256
#define Ww 512
#define Bn 4
#define SPANK 11
#define TBX 32
#define TBY 16
#define HX (TBX + 2*SPANK)   // 54
#define HY (TBY + SPANK)     // 27
#define NOFF 242             // dx in [1,11], dy in [-11,11]\{0}
#define NPIX (Bn*Hh*Ww)      // 524288

// ---------------- device scratch (no allocations allowed) ----------------
__device__ float4 g_P1[NPIX];   // {r/0.1, g/0.1, b/0.1, depth/0.2}
__device__ float4 g_P2[NPIX];   // {y0, y1, y2, dst}
__device__ double g_accF[NOFF], g_accB[NOFF], g_denF[NOFF], g_denB[NOFF];
__device__ double g_ce[3];      // {sum Lce*dst, sum Lce, sum dst}

__device__ __forceinline__ float ex2(float x) {
    float y;
    asm("ex2.approx.ftz.f32 %0, %1;" : "=f"(y) : "f"(x));
    return y;
}

// ---------------- kernel 0: zero accumulators ----------------
__global__ void k_zero() {
    int t = threadIdx.x;
    for (int i = t; i < NOFF; i += blockDim.x) {
        g_accF[i] = 0.0; g_accB[i] = 0.0; g_denF[i] = 0.0; g_denB[i] = 0.0;
    }
    if (t < 3) g_ce[t] = 0.0;
}

// ---------------- kernel 1: softmax prep + CE partial sums ----------------
__global__ void k_prep(const float* __restrict__ logit,
                       const long long* __restrict__ target,
                       const float* __restrict__ image,
                       const float* __restrict__ depth,
                       const float* __restrict__ dstm) {
    int idx = blockIdx.x * blockDim.x + threadIdx.x;
    float ce_d = 0.f, ce_a = 0.f, d_s = 0.f;
    if (idx < NPIX) {
        int b = idx / (Hh * Ww);
        int p = idx - b * (Hh * Ww);
        const float* lg = logit + (size_t)b * 3 * Hh * Ww + p;
        float l0 = lg[0], l1 = lg[Hh * Ww], l2 = lg[2 * Hh * Ww];
        float m = fmaxf(l0, fmaxf(l1, l2));
        float e0 = __expf(l0 - m), e1 = __expf(l1 - m), e2 = __expf(l2 - m);
        float s = e0 + e1 + e2;
        float inv = 1.f / s;
        const float* im = image + (size_t)b * 3 * Hh * Ww + p;
        float dv = dstm[idx];
        g_P1[idx] = make_float4(im[0] * 10.f, im[Hh * Ww] * 10.f,
                                im[2 * Hh * Ww] * 10.f, depth[idx] * 5.f);
        g_P2[idx] = make_float4(e0 * inv, e1 * inv, e2 * inv, dv);
        long long t = target[idx];
        float lt = (t == 0) ? l0 : ((t == 1) ? l1 : l2);
        float lce = m + __logf(s) - lt;     // -log_softmax[target]
        ce_d = lce * dv; ce_a = lce; d_s = dv;
    }
    // warp reduce
    #pragma unroll
    for (int s = 16; s; s >>= 1) {
        ce_d += __shfl_xor_sync(0xffffffffu, ce_d, s);
        ce_a += __shfl_xor_sync(0xffffffffu, ce_a, s);
        d_s  += __shfl_xor_sync(0xffffffffu, d_s,  s);
    }
    __shared__ float r0[8], r1[8], r2[8];
    int lane = threadIdx.x & 31, w = threadIdx.x >> 5;
    if (lane == 0) { r0[w] = ce_d; r1[w] = ce_a; r2[w] = d_s; }
    __syncthreads();
    if (threadIdx.x == 0) {
        float a = 0.f, bb = 0.f, c = 0.f;
        #pragma unroll
        for (int i = 0; i < 8; i++) { a += r0[i]; bb += r1[i]; c += r2[i]; }
        atomicAdd(&g_ce[0], (double)a);
        atomicAdd(&g_ce[1], (double)bb);
        atomicAdd(&g_ce[2], (double)c);
    }
}

// ---------------- kernel 2: CRF pair sums ----------------
__global__ __launch_bounds__(128, 4) void k_crf() {
    __shared__ float4 sA[HY][HX];
    __shared__ float4 sB[HY][HX];
    int b  = blockIdx.z;
    int r0 = blockIdx.y * TBY;
    int c0 = blockIdx.x * TBX;
    int tx = threadIdx.x, ty = threadIdx.y;
    int tid = ty * 32 + tx;

    // load halo (zeros outside image: kills both m-gates and compat exactly)
    for (int i = tid; i < HY * HX; i += 128) {
        int hy = i / HX, hx = i - hy * HX;
        int gy = r0 - SPANK + hy;
        int gx = c0 - SPANK + hx;
        float4 a = make_float4(0.f, 0.f, 0.f, 0.f);
        float4 c = a;
        if (gy >= 0 && gy < Hh && gx >= 0 && gx < Ww) {
            int g = (b * Hh + gy) * Ww + gx;
            a = g_P1[g]; c = g_P2[g];
        }
        sA[hy][hx] = a; sB[hy][hx] = c;
    }
    __syncthreads();

    float4 o1[4], o2[4];
    #pragma unroll
    for (int p = 0; p < 4; p++) {
        o1[p] = sA[SPANK + ty + 4 * p][SPANK + tx];
        o2[p] = sB[SPANK + ty + 4 * p][SPANK + tx];
    }

    const float A2 = -0.7213475204444817f;   // -0.5 * log2(e)
    for (int dx = 1; dx <= SPANK; dx++) {
        for (int dyi = 0; dyi < 22; dyi++) {
            int dy = dyi - SPANK;
            dy += (dy >= 0);                 // skip dy==0
            float cd2 = A2 * (float)(dx * dx + dy * dy) * (1.f / 36.f);
            float accF = 0.f, accB = 0.f, denF = 0.f, denB = 0.f;
            #pragma unroll
            for (int p = 0; p < 4; p++) {
                int vy = SPANK + ty + 4 * p - dx;
                int vx = SPANK + tx - dy;
                float4 v1 = sA[vy][vx];
                float4 v2 = sB[vy][vx];
                float s1v = (v2.x + v2.y) + v2.z;       // 0 outside image
                float dr = o1[p].x - v1.x;
                float dg = o1[p].y - v1.y;
                float db = o1[p].z - v1.z;
                float dz = o1[p].w - v1.w;
                float sq = dr * dr;
                sq = fmaf(dg, dg, sq);
                sq = fmaf(db, db, sq);
                float k = ex2(fmaf(sq, A2, cd2)) + ex2(dz * dz * A2);
                float compat = s1v;                      // s1_u ~= 1
                compat = fmaf(-o2[p].x, v2.x, compat);
                compat = fmaf(-o2[p].y, v2.y, compat);
                compat = fmaf(-o2[p].z, v2.z, compat);
                float kc = k * compat;
                accF = fmaf(kc, v2.w, accF);             // N(+d): dst at far pixel
                accB = fmaf(kc, o2[p].w, accB);          // N(-d): dst at near pixel (compat=0 gates invalid)
                denF += v2.w;                            // D(+d) exact
                denB = fmaf(o2[p].w, s1v, denB);         // D(-d), s1v as validity (~1e-7 err)
            }
            #pragma unroll
            for (int s = 16; s; s >>= 1) {
                accF += __shfl_xor_sync(0xffffffffu, accF, s);
                accB += __shfl_xor_sync(0xffffffffu, accB, s);
                denF += __shfl_xor_sync(0xffffffffu, denF, s);
                denB += __shfl_xor_sync(0xffffffffu, denB, s);
            }
            if (tx == 0) {
                int off = (dx - 1) * 22 + dyi;
                atomicAdd(&g_accF[off], (double)accF);
                atomicAdd(&g_accB[off], (double)accB);
                atomicAdd(&g_denF[off], (double)denF);
                atomicAdd(&g_denB[off], (double)denB);
            }
        }
    }
}

// ---------------- kernel 3: finalize ----------------
__global__ void k_final(float* __restrict__ out) {
    __shared__ double red[256];
    int t = threadIdx.x;
    double e = 0.0;
    if (t < NOFF) {
        e = g_accF[t] / g_denF[t] + g_accB[t] / g_denB[t];
    }
    red[t] = e;
    __syncthreads();
    for (int s = 128; s; s >>= 1) {
        if (t < s) red[t] += red[t + s];
        __syncthreads();
    }
    if (t == 0) {
        out[1] = (float)(red[0] / 529.0);    // grid.mean over 23x23
        double N = (double)NPIX;
        double SA = g_ce[0], SB = g_ce[1], SC = g_ce[2];
        double lo1 = SA / N;
        double lo2 = (SB - SA) / N;
        double cnt = SC / N;
        out[0] = (float)(lo1 * (1.0 - cnt) + lo2 * cnt);
    }
}

// ---------------- entry point ----------------
extern "C" void kernel_launch(void* const* d_in, const int* in_sizes, int n_in,
                              void* d_out, int out_size) {
    (void)in_sizes; (void)n_in; (void)out_size;
    const float*     logit  = (const float*)d_in[0];
    const long long* target = (const long long*)d_in[1];
    const float*     image  = (const float*)d_in[2];
    const float*     depth  = (const float*)d_in[3];
    const float*     dstm   = (const float*)d_in[4];
    float* out = (float*)d_out;

    k_zero<<<1, 256>>>();
    k_prep<<<NPIX / 256, 256>>>(logit, target, image, depth, dstm);
    dim3 blk(32, 4);
    dim3 grd(Ww / TBX, Hh / TBY, Bn);
    k_crf<<<grd, blk>>>();
    k_final<<<1, 256>>>(out);
}

// round 2
// speedup vs baseline: 1.7908x; 1.7908x over previous
#include <cuda_runtime.h>

#define Hh 256
#define Ww 512
#define Bn 4
#define SPANK 11
#define TBX 32
#define TBY 16
#define HX (TBX + 2*SPANK)   // 54
#define HY (TBY + SPANK)     // 27
#define NOFF 242             // dx in [1,11], dy in [-11,11]\{0}
#define NPIX (Bn*Hh*Ww)      // 524288
#define PLANE_BYTES (HY*HX*16)   // 23328

// ---------------- device scratch (no allocations allowed) ----------------
__device__ float4 g_P1[NPIX];   // {r*10, g*10, b*10, depth*5}
__device__ float4 g_P2[NPIX];   // {y0, y1, y2, dst}
__device__ double g_accF[NOFF], g_accB[NOFF];
__device__ double g_ce[3];      // {sum Lce*dst, sum Lce, sum dst}
// denominator pipeline scratch
__device__ float  g_rowFull[Hh];
__device__ float  g_rowHead[Hh][12];   // head[c] = sum_{y<c}, c=0..11
__device__ float  g_rowTail[Hh][12];   // tail[e] = sum_{y>=W-e}, e=0..11
__device__ double g_rect[23*23];       // rect[(dx+11)*23 + (dy+11)]

__device__ __forceinline__ float ex2(float x) {
    float y;
    asm("ex2.approx.ftz.f32 %0, %1;" : "=f"(y) : "f"(x));
    return y;
}

// ---------------- kernel 0: zero accumulators ----------------
__global__ void k_zero() {
    int t = threadIdx.x;
    for (int i = t; i < NOFF; i += blockDim.x) {
        g_accF[i] = 0.0; g_accB[i] = 0.0;
    }
    if (t < 3) g_ce[t] = 0.0;
}

// ---------------- kernel 1: softmax prep + CE partial sums ----------------
__global__ void k_prep(const float* __restrict__ logit,
                       const long long* __restrict__ target,
                       const float* __restrict__ image,
                       const float* __restrict__ depth,
                       const float* __restrict__ dstm) {
    int idx = blockIdx.x * blockDim.x + threadIdx.x;
    float ce_d = 0.f, ce_a = 0.f, d_s = 0.f;
    if (idx < NPIX) {
        int b = idx / (Hh * Ww);
        int p = idx - b * (Hh * Ww);
        const float* lg = logit + (size_t)b * 3 * Hh * Ww + p;
        float l0 = lg[0], l1 = lg[Hh * Ww], l2 = lg[2 * Hh * Ww];
        float m = fmaxf(l0, fmaxf(l1, l2));
        float e0 = __expf(l0 - m), e1 = __expf(l1 - m), e2 = __expf(l2 - m);
        float s = e0 + e1 + e2;
        float inv = 1.f / s;
        const float* im = image + (size_t)b * 3 * Hh * Ww + p;
        float dv = dstm[idx];
        g_P1[idx] = make_float4(im[0] * 10.f, im[Hh * Ww] * 10.f,
                                im[2 * Hh * Ww] * 10.f, depth[idx] * 5.f);
        g_P2[idx] = make_float4(e0 * inv, e1 * inv, e2 * inv, dv);
        long long t = target[idx];
        float lt = (t == 0) ? l0 : ((t == 1) ? l1 : l2);
        float lce = m + __logf(s) - lt;     // -log_softmax[target]
        ce_d = lce * dv; ce_a = lce; d_s = dv;
    }
    #pragma unroll
    for (int s = 16; s; s >>= 1) {
        ce_d += __shfl_xor_sync(0xffffffffu, ce_d, s);
        ce_a += __shfl_xor_sync(0xffffffffu, ce_a, s);
        d_s  += __shfl_xor_sync(0xffffffffu, d_s,  s);
    }
    __shared__ float r0[8], r1[8], r2[8];
    int lane = threadIdx.x & 31, w = threadIdx.x >> 5;
    if (lane == 0) { r0[w] = ce_d; r1[w] = ce_a; r2[w] = d_s; }
    __syncthreads();
    if (threadIdx.x == 0) {
        float a = 0.f, bb = 0.f, c = 0.f;
        #pragma unroll
        for (int i = 0; i < 8; i++) { a += r0[i]; bb += r1[i]; c += r2[i]; }
        atomicAdd(&g_ce[0], (double)a);
        atomicAdd(&g_ce[1], (double)bb);
        atomicAdd(&g_ce[2], (double)c);
    }
}

// ---------------- kernel 1b: per-row dst aggregates (for exact denominators) ----
__global__ void k_rows(const float* __restrict__ dstm) {
    int x = blockIdx.x;                // row 0..255
    int tid = threadIdx.x;             // 128 threads
    float psum = 0.f;
    for (int b = 0; b < Bn; b++) {
        const float* row = dstm + ((size_t)b * Hh + x) * Ww;
        for (int y = tid; y < Ww; y += 128) psum += row[y];
    }
    #pragma unroll
    for (int s = 16; s; s >>= 1) psum += __shfl_xor_sync(0xffffffffu, psum, s);
    __shared__ float wsum[4];
    int lane = tid & 31, w = tid >> 5;
    if (lane == 0) wsum[w] = psum;
    __syncthreads();
    if (tid == 0) {
        double full = (double)wsum[0] + wsum[1] + wsum[2] + wsum[3];
        g_rowFull[x] = (float)full;
        // heads: head[c] = sum over y<c (c=0..11)
        double h = 0.0;
        g_rowHead[x][0] = 0.f;
        for (int y = 0; y < SPANK; y++) {
            for (int b = 0; b < Bn; b++)
                h += dstm[((size_t)b * Hh + x) * Ww + y];
            g_rowHead[x][y + 1] = (float)h;
        }
        double t = 0.0;
        g_rowTail[x][0] = 0.f;
        for (int e = 1; e <= SPANK; e++) {
            for (int b = 0; b < Bn; b++)
                t += dstm[((size_t)b * Hh + x) * Ww + (Ww - e)];
            g_rowTail[x][e] = (float)t;
        }
    }
}

// ---------------- kernel 1c: rectangle sums (all 23x23 denominators) ----------
__global__ void k_rect() {
    __shared__ float sR[23][Hh];          // per y-range, per row
    __shared__ double sFull[23], sHead[23][12], sTail[23][12];
    int tid = threadIdx.x;                // 256 threads
    // phase 1: each thread = one row x; compute 23 y-range row sums
    {
        int x = tid;
        float full = g_rowFull[x];
        float head[12], tail[12];
        #pragma unroll
        for (int i = 0; i < 12; i++) { head[i] = g_rowHead[x][i]; tail[i] = g_rowTail[x][i]; }
        #pragma unroll
        for (int yi = 0; yi < 23; yi++) {
            int dy = yi - SPANK;
            int c = dy < 0 ? -dy : 0;
            int e = dy > 0 ? dy : 0;
            sR[yi][x] = full - head[c] - tail[e];
        }
    }
    __syncthreads();
    // phase 2: column (x-direction) prefix aggregates per y-range
    if (tid < 23) {
        int yi = tid;
        double s = 0.0;
        double pref_tail[12];
        double headArr[12];
        headArr[0] = 0.0;
        for (int x = 0; x < Hh; x++) {
            if (x >= 1 && x <= SPANK) headArr[x] = s;   // head[a]=sum_{x<a}, a=x here
            if (x >= Hh - SPANK) pref_tail[Hh - x] = s; // prefix at x=Hh-b -> index b
            s += (double)sR[yi][x];
        }
        sFull[yi] = s;
        sHead[yi][0] = 0.0;
        #pragma unroll
        for (int a = 1; a <= SPANK; a++) sHead[yi][a] = headArr[a];
        sTail[yi][0] = 0.0;
        #pragma unroll
        for (int b = 1; b <= SPANK; b++) sTail[yi][b] = s - pref_tail[b];
    }
    __syncthreads();
    // phase 3: 529 rectangle sums
    for (int t = tid; t < 23 * 23; t += 256) {
        int xi = t / 23, yi = t - xi * 23;
        int dx = xi - SPANK;
        int a = dx < 0 ? -dx : 0;
        int b = dx > 0 ? dx : 0;
        g_rect[t] = sFull[yi] - sHead[yi][a] - sTail[yi][b];
    }
}

// ---------------- kernel 2: CRF pair sums (lanes = offsets) ----------------
__global__ __launch_bounds__(128, 4) void k_crf() {
    __shared__ float4 sAB[2][HY][HX];     // 46656 bytes
    int b  = blockIdx.z;
    int r0 = blockIdx.y * TBY;
    int c0 = blockIdx.x * TBX;
    int lane = threadIdx.x;               // 0..31
    int w    = threadIdx.y;               // 0..3
    int tid  = w * 32 + lane;

    // load halo (zeros outside image: compat=0 gates those pairs exactly)
    for (int i = tid; i < HY * HX; i += 128) {
        int hy = i / HX, hx = i - hy * HX;
        int gy = r0 - SPANK + hy;
        int gx = c0 - SPANK + hx;
        float4 a = make_float4(0.f, 0.f, 0.f, 0.f);
        float4 c = a;
        if (gy >= 0 && gy < Hh && gx >= 0 && gx < Ww) {
            int g = (b * Hh + gy) * Ww + gx;
            a = g_P1[g]; c = g_P2[g];
        }
        sAB[0][hy][hx] = a; sAB[1][hy][hx] = c;
    }
    __syncthreads();

    const float A2 = -0.7213475204444817f;   // -0.5 * log2(e)
    // per-lane offset tables: id = g*32+lane -> (dx,dy)
    float cd2[8];
    int   deltaB[8];
    #pragma unroll
    for (int g = 0; g < 8; g++) {
        int id = g * 32 + lane;
        int dx = 0, dy = 0;
        if (id < NOFF) {
            dx = id / 22 + 1;
            int r = id - (dx - 1) * 22;
            dy = r - SPANK;
            dy += (dy >= 0);
        }
        cd2[g] = A2 * (float)(dx * dx + dy * dy) * (1.f / 36.f);
        deltaB[g] = (dx * HX + dy) * 16;
    }

    float accF[8], accB[8];
    #pragma unroll
    for (int g = 0; g < 8; g++) { accF[g] = 0.f; accB[g] = 0.f; }

    const char* base = (const char*)&sAB[0][0][0];
    // warp w owns tile rows [4w, 4w+4)
    for (int rr = 0; rr < 4; rr++) {
        int oy = SPANK + 4 * w + rr;
        int oB0 = (oy * HX + SPANK) * 16;
        for (int px = 0; px < TBX; px++) {
            int oB = oB0 + px * 16;
            float4 o1 = *(const float4*)(base + oB);
            float4 o2 = *(const float4*)(base + oB + PLANE_BYTES);
            float o2x = o2.x, o2y = o2.y, o2z = o2.z, o2w = o2.w;
            #pragma unroll
            for (int g = 0; g < 8; g++) {
                int vB = oB - deltaB[g];
                float4 v1 = *(const float4*)(base + vB);
                float4 v2 = *(const float4*)(base + vB + PLANE_BYTES);
                float dr = o1.x - v1.x;
                float dg = o1.y - v1.y;
                float db = o1.z - v1.z;
                float dz = o1.w - v1.w;
                float sq = dr * dr;
                sq = fmaf(dg, dg, sq);
                sq = fmaf(db, db, sq);
                float arg1 = fmaf(sq, A2, cd2[g]);
                float dzA = dz * A2;
                float k = ex2(arg1) + ex2(dzA * dz);
                float compat = (v2.x + v2.y) + v2.z;      // s1_v (0 in halo)
                compat = fmaf(-o2x, v2.x, compat);
                compat = fmaf(-o2y, v2.y, compat);
                compat = fmaf(-o2z, v2.z, compat);
                float kc = k * compat;
                accF[g] = fmaf(kc, v2.w, accF[g]);        // numerator for +d
                accB[g] = fmaf(kc, o2w,  accB[g]);        // numerator for -d
            }
        }
    }

    // ---- CTA reduction, reusing the halo smem ----
    __syncthreads();
    float* red = (float*)&sAB[0][0][0];   // [256 offsets][4 warps][2]
    #pragma unroll
    for (int g = 0; g < 8; g++) {
        int id = g * 32 + lane;
        red[(id * 4 + w) * 2 + 0] = accF[g];
        red[(id * 4 + w) * 2 + 1] = accB[g];
    }
    __syncthreads();
    for (int o = tid; o < NOFF; o += 128) {
        float f = red[o * 8 + 0] + red[o * 8 + 2] + red[o * 8 + 4] + red[o * 8 + 6];
        float bb = red[o * 8 + 1] + red[o * 8 + 3] + red[o * 8 + 5] + red[o * 8 + 7];
        atomicAdd(&g_accF[o], (double)f);
        atomicAdd(&g_accB[o], (double)bb);
    }
}

// ---------------- kernel 3: finalize ----------------
__global__ void k_final(float* __restrict__ out) {
    __shared__ double red[256];
    int t = threadIdx.x;
    double e = 0.0;
    if (t < NOFF) {
        int dx = t / 22 + 1;
        int r = t - (dx - 1) * 22;
        int dy = r - SPANK;
        dy += (dy >= 0);
        double denF = g_rect[(SPANK - dx) * 23 + (SPANK - dy)];
        double denB = g_rect[(SPANK + dx) * 23 + (SPANK + dy)];
        e = g_accF[t] / denF + g_accB[t] / denB;
    }
    red[t] = e;
    __syncthreads();
    for (int s = 128; s; s >>= 1) {
        if (t < s) red[t] += red[t + s];
        __syncthreads();
    }
    if (t == 0) {
        out[1] = (float)(red[0] / 529.0);    // grid.mean over 23x23
        double N = (double)NPIX;
        double SA = g_ce[0], SB = g_ce[1], SC = g_ce[2];
        double lo1 = SA / N;
        double lo2 = (SB - SA) / N;
        double cnt = SC / N;
        out[0] = (float)(lo1 * (1.0 - cnt) + lo2 * cnt);
    }
}

// ---------------- entry point ----------------
extern "C" void kernel_launch(void* const* d_in, const int* in_sizes, int n_in,
                              void* d_out, int out_size) {
    (void)in_sizes; (void)n_in; (void)out_size;
    const float*     logit  = (const float*)d_in[0];
    const long long* target = (const long long*)d_in[1];
    const float*     image  = (const float*)d_in[2];
    const float*     depth  = (const float*)d_in[3];
    const float*     dstm   = (const float*)d_in[4];
    float* out = (float*)d_out;

    k_zero<<<1, 256>>>();
    k_prep<<<NPIX / 256, 256>>>(logit, target, image, depth, dstm);
    k_rows<<<Hh, 128>>>(dstm);
    k_rect<<<1, 256>>>();
    dim3 blk(32, 4);
    dim3 grd(Ww / TBX, Hh / TBY, Bn);
    k_crf<<<grd, blk>>>();
    k_final<<<1, 256>>>(out);
}

// round 3
// speedup vs baseline: 2.4995x; 1.3958x over previous
#include <cuda_runtime.h>
#include <cuda_fp16.h>

#define Hh 256
#define Ww 512
#define Bn 4
#define SPANK 11
#define TBX 32
#define TBY 16
#define HX (TBX + 2*SPANK)   // 54
#define HY (TBY + SPANK)     // 27
#define NOFF 242             // dx in [1,11], dy in [-11,11]\{0}
#define NPIX (Bn*Hh*Ww)      // 524288

// scales: RGB*10, depth*5, both folded with sqrt(0.5*log2(e)) = 0.8493218083
#define RGB_S 8.493218083f
#define DEP_S 4.2466090415f

// ---------------- device scratch (no allocations allowed) ----------------
__device__ uint4  g_PK[NPIX];   // packed halves {r,g | b,z | y0,y1 | y2,dst}
__device__ double g_accF[NOFF], g_accB[NOFF];
__device__ double g_ce[3];      // {sum Lce*dst, sum Lce, sum dst}
__device__ float  g_rowFull[Hh];
__device__ float  g_rowHead[Hh][12];   // head[c] = sum_{y<c}
__device__ float  g_rowTail[Hh][12];   // tail[e] = sum_{y>=W-e}

__device__ __forceinline__ float ex2(float x) {
    float y;
    asm("ex2.approx.ftz.f32 %0, %1;" : "=f"(y) : "f"(x));
    return y;
}

// ---------------- kernel 0: zero accumulators ----------------
__global__ void k_zero() {
    int t = threadIdx.x;
    for (int i = t; i < NOFF; i += blockDim.x) {
        g_accF[i] = 0.0; g_accB[i] = 0.0;
    }
    if (t < 3) g_ce[t] = 0.0;
}

// ---------------- kernel 1: softmax prep (packed fp16) + CE partials --------
__global__ void k_prep(const float* __restrict__ logit,
                       const long long* __restrict__ target,
                       const float* __restrict__ image,
                       const float* __restrict__ depth,
                       const float* __restrict__ dstm) {
    int idx = blockIdx.x * blockDim.x + threadIdx.x;
    float ce_d = 0.f, ce_a = 0.f, d_s = 0.f;
    if (idx < NPIX) {
        int b = idx / (Hh * Ww);
        int p = idx - b * (Hh * Ww);
        const float* lg = logit + (size_t)b * 3 * Hh * Ww + p;
        float l0 = lg[0], l1 = lg[Hh * Ww], l2 = lg[2 * Hh * Ww];
        float m = fmaxf(l0, fmaxf(l1, l2));
        float e0 = __expf(l0 - m), e1 = __expf(l1 - m), e2 = __expf(l2 - m);
        float s = e0 + e1 + e2;
        float inv = 1.f / s;
        const float* im = image + (size_t)b * 3 * Hh * Ww + p;
        float dv = dstm[idx];
        __half2 h0 = __floats2half2_rn(im[0] * RGB_S, im[Hh * Ww] * RGB_S);
        __half2 h1 = __floats2half2_rn(im[2 * Hh * Ww] * RGB_S, depth[idx] * DEP_S);
        __half2 h2 = __floats2half2_rn(e0 * inv, e1 * inv);
        __half2 h3 = __floats2half2_rn(e2 * inv, dv);
        uint4 pk;
        pk.x = *(unsigned*)&h0; pk.y = *(unsigned*)&h1;
        pk.z = *(unsigned*)&h2; pk.w = *(unsigned*)&h3;
        g_PK[idx] = pk;
        long long t = target[idx];
        float lt = (t == 0) ? l0 : ((t == 1) ? l1 : l2);
        float lce = m + __logf(s) - lt;     // -log_softmax[target]
        ce_d = lce * dv; ce_a = lce; d_s = dv;
    }
    #pragma unroll
    for (int s = 16; s; s >>= 1) {
        ce_d += __shfl_xor_sync(0xffffffffu, ce_d, s);
        ce_a += __shfl_xor_sync(0xffffffffu, ce_a, s);
        d_s  += __shfl_xor_sync(0xffffffffu, d_s,  s);
    }
    __shared__ float r0[8], r1[8], r2[8];
    int lane = threadIdx.x & 31, w = threadIdx.x >> 5;
    if (lane == 0) { r0[w] = ce_d; r1[w] = ce_a; r2[w] = d_s; }
    __syncthreads();
    if (threadIdx.x == 0) {
        float a = 0.f, bb = 0.f, c = 0.f;
        #pragma unroll
        for (int i = 0; i < 8; i++) { a += r0[i]; bb += r1[i]; c += r2[i]; }
        atomicAdd(&g_ce[0], (double)a);
        atomicAdd(&g_ce[1], (double)bb);
        atomicAdd(&g_ce[2], (double)c);
    }
}

// ---------------- kernel 1b: per-row dst aggregates ----------------
__global__ void k_rows(const float* __restrict__ dstm) {
    int x = blockIdx.x;                // row 0..255
    int tid = threadIdx.x;             // 128 threads
    int lane = tid & 31, w = tid >> 5;
    float psum = 0.f;
    for (int b = 0; b < Bn; b++) {
        const float* row = dstm + ((size_t)b * Hh + x) * Ww;
        for (int y = tid; y < Ww; y += 128) psum += row[y];
    }
    #pragma unroll
    for (int s = 16; s; s >>= 1) psum += __shfl_xor_sync(0xffffffffu, psum, s);
    __shared__ float wsum[4];
    if (lane == 0) wsum[w] = psum;
    __syncthreads();
    if (tid == 0)
        g_rowFull[x] = wsum[0] + wsum[1] + wsum[2] + wsum[3];
    if (tid < 32 && lane <= SPANK) {
        float h = 0.f;
        for (int y = 0; y < lane; y++)
            for (int b = 0; b < Bn; b++)
                h += dstm[((size_t)b * Hh + x) * Ww + y];
        g_rowHead[x][lane] = h;
        float t = 0.f;
        for (int e = 1; e <= lane; e++)
            for (int b = 0; b < Bn; b++)
                t += dstm[((size_t)b * Hh + x) * Ww + (Ww - e)];
        g_rowTail[x][lane] = t;
    }
}

// ---------------- kernel 2: CRF pair sums (lanes = offsets) ----------------
__global__ __launch_bounds__(128, 8) void k_crf() {
    __shared__ uint4 sP[HY][HX];          // 23328 bytes
    int b  = blockIdx.z;
    int r0 = blockIdx.y * TBY;
    int c0 = blockIdx.x * TBX;
    int lane = threadIdx.x;               // 0..31
    int w    = threadIdx.y;               // 0..3
    int tid  = w * 32 + lane;

    // load halo (zeros outside image: y's=0 -> compat=0 gates those pairs)
    for (int i = tid; i < HY * HX; i += 128) {
        int hy = i / HX, hx = i - hy * HX;
        int gy = r0 - SPANK + hy;
        int gx = c0 - SPANK + hx;
        uint4 a = make_uint4(0u, 0u, 0u, 0u);
        if (gy >= 0 && gy < Hh && gx >= 0 && gx < Ww)
            a = g_PK[(b * Hh + gy) * Ww + gx];
        sP[hy][hx] = a;
    }
    __syncthreads();

    const float A2 = -0.7213475204444817f;   // -0.5 * log2(e)
    float cd2[8];
    int   deltaB[8];
    #pragma unroll
    for (int g = 0; g < 8; g++) {
        int id = g * 32 + lane;
        int dx = 0, dy = 0;
        if (id < NOFF) {
            dx = id / 22 + 1;
            int r = id - (dx - 1) * 22;
            dy = r - SPANK;
            dy += (dy >= 0);
        }
        cd2[g] = A2 * (float)(dx * dx + dy * dy) * (1.f / 36.f);
        deltaB[g] = (dx * HX + dy) * 16;
    }

    float accF[8], accB[8];
    #pragma unroll
    for (int g = 0; g < 8; g++) { accF[g] = 0.f; accB[g] = 0.f; }

    const char* base = (const char*)&sP[0][0];
    for (int rr = 0; rr < 4; rr++) {
        int oy = SPANK + 4 * w + rr;
        int oB0 = (oy * HX + SPANK) * 16;
        for (int px = 0; px < TBX; px++) {
            int oB = oB0 + px * 16;
            uint4 o = *(const uint4*)(base + oB);
            float2 org  = __half22float2(*(const __half2*)&o.x);
            float2 obz  = __half22float2(*(const __half2*)&o.y);
            float2 oy01 = __half22float2(*(const __half2*)&o.z);
            float2 oy2d = __half22float2(*(const __half2*)&o.w);
            #pragma unroll
            for (int g = 0; g < 8; g++) {
                uint4 v = *(const uint4*)(base + (oB - deltaB[g]));
                float2 vrg  = __half22float2(*(const __half2*)&v.x);
                float2 vbz  = __half22float2(*(const __half2*)&v.y);
                float2 vy01 = __half22float2(*(const __half2*)&v.z);
                float2 vy2d = __half22float2(*(const __half2*)&v.w);
                float dr = org.x - vrg.x;
                float dg = org.y - vrg.y;
                float db = obz.x - vbz.x;
                float dz = obz.y - vbz.y;
                float s = fmaf(dr, -dr, cd2[g]);
                s = fmaf(dg, -dg, s);
                s = fmaf(db, -db, s);
                float arg2 = dz * -dz;
                float k = ex2(s) + ex2(arg2);
                float s1v = (vy01.x + vy01.y) + vy2d.x;   // 0 in halo
                float compat = fmaf(-oy01.x, vy01.x, s1v);
                compat = fmaf(-oy01.y, vy01.y, compat);
                compat = fmaf(-oy2d.x, vy2d.x, compat);
                float kc = k * compat;
                accF[g] = fmaf(kc, vy2d.y, accF[g]);      // +d numerator
                accB[g] = fmaf(kc, oy2d.y, accB[g]);      // -d numerator
            }
        }
    }

    // ---- CTA reduction, reusing halo smem ----
    __syncthreads();
    float* red = (float*)&sP[0][0];       // [256][4 warps][2] = 8KB
    #pragma unroll
    for (int g = 0; g < 8; g++) {
        int id = g * 32 + lane;
        red[(id * 4 + w) * 2 + 0] = accF[g];
        red[(id * 4 + w) * 2 + 1] = accB[g];
    }
    __syncthreads();
    for (int o = tid; o < NOFF; o += 128) {
        float f  = red[o * 8 + 0] + red[o * 8 + 2] + red[o * 8 + 4] + red[o * 8 + 6];
        float bb = red[o * 8 + 1] + red[o * 8 + 3] + red[o * 8 + 5] + red[o * 8 + 7];
        atomicAdd(&g_accF[o], (double)f);
        atomicAdd(&g_accB[o], (double)bb);
    }
}

// ---------------- kernel 3: rect sums + finalize ----------------
__global__ void k_final(float* __restrict__ out) {
    __shared__ float  sR[23][Hh];              // 23.5 KB
    __shared__ double sFull[23], sHead[23][12], sTail[23][12];
    __shared__ double rect[23 * 23];
    __shared__ double red[256];
    int tid = threadIdx.x;                     // 256 threads
    int lane = tid & 31, w8 = tid >> 5;

    // phase 1: one thread per row x -> 23 y-range row sums
    {
        int x = tid;
        float full = g_rowFull[x];
        float head[12], tail[12];
        #pragma unroll
        for (int i = 0; i < 12; i++) { head[i] = g_rowHead[x][i]; tail[i] = g_rowTail[x][i]; }
        #pragma unroll
        for (int yi = 0; yi < 23; yi++) {
            int dy = yi - SPANK;
            int c = dy < 0 ? -dy : 0;
            int e = dy > 0 ? dy : 0;
            sR[yi][x] = full - head[c] - tail[e];
        }
    }
    __syncthreads();

    // phase 2: per y-range column aggregates (warp per yi)
    for (int yi = w8; yi < 23; yi += 8) {
        float p = 0.f;
        for (int x = lane; x < Hh; x += 32) p += sR[yi][x];
        #pragma unroll
        for (int s = 16; s; s >>= 1) p += __shfl_xor_sync(0xffffffffu, p, s);
        if (lane == 0) sFull[yi] = (double)p;
        if (lane <= SPANK) {
            float h = 0.f;
            for (int x = 0; x < lane; x++) h += sR[yi][x];
            sHead[yi][lane] = (double)h;
            float t = 0.f;
            for (int e = 1; e <= lane; e++) t += sR[yi][Hh - e];
            sTail[yi][lane] = (double)t;
        }
    }
    __syncthreads();

    // phase 3: 529 rectangle sums
    for (int t = tid; t < 23 * 23; t += 256) {
        int xi = t / 23, yi = t - xi * 23;
        int dx = xi - SPANK;
        int a = dx < 0 ? -dx : 0;
        int bb = dx > 0 ? dx : 0;
        rect[t] = sFull[yi] - sHead[yi][a] - sTail[yi][bb];
    }
    __syncthreads();

    // phase 4: energies + reduction
    double e = 0.0;
    if (tid < NOFF) {
        int dx = tid / 22 + 1;
        int r = tid - (dx - 1) * 22;
        int dy = r - SPANK;
        dy += (dy >= 0);
        double denF = rect[(SPANK - dx) * 23 + (SPANK - dy)];
        double denB = rect[(SPANK + dx) * 23 + (SPANK + dy)];
        e = g_accF[tid] / denF + g_accB[tid] / denB;
    }
    red[tid] = e;
    __syncthreads();
    for (int s = 128; s; s >>= 1) {
        if (tid < s) red[tid] += red[tid + s];
        __syncthreads();
    }
    if (tid == 0) {
        out[1] = (float)(red[0] / 529.0);
        double N = (double)NPIX;
        double SA = g_ce[0], SB = g_ce[1], SC = g_ce[2];
        double lo1 = SA / N;
        double lo2 = (SB - SA) / N;
        double cnt = SC / N;
        out[0] = (float)(lo1 * (1.0 - cnt) + lo2 * cnt);
    }
}

// ---------------- entry point ----------------
extern "C" void kernel_launch(void* const* d_in, const int* in_sizes, int n_in,
                              void* d_out, int out_size) {
    (void)in_sizes; (void)n_in; (void)out_size;
    const float*     logit  = (const float*)d_in[0];
    const long long* target = (const long long*)d_in[1];
    const float*     image  = (const float*)d_in[2];
    const float*     depth  = (const float*)d_in[3];
    const float*     dstm   = (const float*)d_in[4];
    float* out = (float*)d_out;

    k_zero<<<1, 256>>>();
    k_prep<<<NPIX / 256, 256>>>(logit, target, image, depth, dstm);
    k_rows<<<Hh, 128>>>(dstm);
    dim3 blk(32, 4);
    dim3 grd(Ww / TBX, Hh / TBY, Bn);
    k_crf<<<grd, blk>>>();
    k_final<<<1, 256>>>(out);
}